// round 6
// baseline (speedup 1.0000x reference)
#include <cuda_runtime.h>

#define N_NODES 50000
#define N_EDGES 800000
#define D 64
#define GRID 592                         // 148 SMs x 4 blocks/SM (one wave incl. 152-SM GB300)
#define TPB 256
#define TILE_ROWS 4
#define NT4 (N_NODES / TILE_ROWS)        // 12500 exact (50000 = 4*12500)
#define CH ((N_NODES + GRID - 1) / GRID) // 85 nodes per block chunk
#define AT_STRIDE 132                    // 128 + 4 pad (breaks bank aliasing between row pairs)

// ---------------- scratch (static device globals; no allocation) ----------------
__device__ int   g_degcnt[N_NODES];
__device__ int   g_cursor[N_NODES];
__device__ int   g_rs[N_NODES + 1];      // CSR row starts
__device__ int   g_csr[N_EDGES];         // CSR column (src) indices
__device__ int   g_bsum[GRID];
__device__ int   g_boff[GRID];
__device__ int   g_tile[2];              // dynamic tile counters (one per layer)
__device__ float g_h[N_NODES * D];

// barrier state: monotonic, never reset (safe across graph replays)
__device__ unsigned g_bcnt = 0;
__device__ unsigned g_bgen = 0;

__device__ __forceinline__ void grid_bar() {
    __syncthreads();
    if (threadIdx.x == 0) {
        __threadfence();
        unsigned my = atomicAdd(&g_bcnt, 1u) + 1u;
        unsigned need = (my + GRID - 1u) / GRID;
        if ((my % GRID) == 0u) atomicAdd(&g_bgen, 1u);
        while (*((volatile unsigned*)&g_bgen) < need) {}
        __threadfence();
    }
    __syncthreads();
}

__device__ __forceinline__ int load_idx(const void* p, int e, bool is64) {
    return is64 ? (int)((const long long*)p)[e] : ((const int*)p)[e];
}

// ---------------- per-warp independent layer: NO block sync inside ----------------
// Each warp grabs 4-row tiles; half-warp gathers 2 rows (self + neighbor-mean) into
// its private smem slice [self(64) | neigh(64)], then a 128-deep GEMM against the
// stacked [Wself; Wneigh] in smem. Gather-latency warps overlap GEMM-compute warps.
template <bool RELU>
__device__ __forceinline__ void run_layer(
    const float* __restrict__ inp, float* __restrict__ outp,
    const float* __restrict__ bias, int lyr,
    float (*Aw)[AT_STRIDE],          // this warp's [TILE_ROWS][AT_STRIDE] slice
    const float* __restrict__ Wsm,   // stacked 128x64 weights in smem
    int lane)
{
    const int half = lane >> 4;
    const int l16  = lane & 15;

    for (;;) {
        int t = 0;
        if (lane == 0) t = atomicAdd(&g_tile[lyr], 1);
        t = __shfl_sync(0xffffffffu, t, 0);
        if (t >= NT4) break;
        const int row0 = t * TILE_ROWS;

        int rsv = 0;
        if (lane < TILE_ROWS + 1) rsv = g_rs[row0 + lane];

        // ---- gather + self: half h owns rows h*2, h*2+1 ----
#pragma unroll
        for (int i = 0; i < 2; i++) {
            const int r  = half * 2 + i;
            const int gr = row0 + r;
            const int beg = __shfl_sync(0xffffffffu, rsv, r);
            const int end = __shfl_sync(0xffffffffu, rsv, r + 1);

            float4 sf = __ldg((const float4*)(inp + (long long)gr * D) + l16);
            *(float4*)&Aw[r][l16 * 4] = sf;

            float4 a0 = make_float4(0.f, 0.f, 0.f, 0.f), a1 = a0, a2 = a0, a3 = a0;
            int e = beg;
            for (; e + 3 < end; e += 4) {
                int s0 = g_csr[e],     s1 = g_csr[e + 1];
                int s2 = g_csr[e + 2], s3 = g_csr[e + 3];
                float4 v0 = __ldg((const float4*)(inp + (long long)s0 * D) + l16);
                float4 v1 = __ldg((const float4*)(inp + (long long)s1 * D) + l16);
                float4 v2 = __ldg((const float4*)(inp + (long long)s2 * D) + l16);
                float4 v3 = __ldg((const float4*)(inp + (long long)s3 * D) + l16);
                a0.x += v0.x; a0.y += v0.y; a0.z += v0.z; a0.w += v0.w;
                a1.x += v1.x; a1.y += v1.y; a1.z += v1.z; a1.w += v1.w;
                a2.x += v2.x; a2.y += v2.y; a2.z += v2.z; a2.w += v2.w;
                a3.x += v3.x; a3.y += v3.y; a3.z += v3.z; a3.w += v3.w;
            }
            for (; e < end; e++) {
                int s0 = g_csr[e];
                float4 v0 = __ldg((const float4*)(inp + (long long)s0 * D) + l16);
                a0.x += v0.x; a0.y += v0.y; a0.z += v0.z; a0.w += v0.w;
            }
            float iv = 1.0f / fmaxf((float)(end - beg), 1.0f);
            float4 m;
            m.x = ((a0.x + a1.x) + (a2.x + a3.x)) * iv;
            m.y = ((a0.y + a1.y) + (a2.y + a3.y)) * iv;
            m.z = ((a0.z + a1.z) + (a2.z + a3.z)) * iv;
            m.w = ((a0.w + a1.w) + (a2.w + a3.w)) * iv;
            *(float4*)&Aw[r][D + l16 * 4] = m;
        }
        __syncwarp();

        // ---- GEMM: rows half*2..half*2+1, cols l16*4..+3, k = 0..127 ----
        const float* A0 = Aw[half * 2];
        const float* A1 = Aw[half * 2 + 1];
        float acc00 = 0.f, acc01 = 0.f, acc02 = 0.f, acc03 = 0.f;
        float acc10 = 0.f, acc11 = 0.f, acc12 = 0.f, acc13 = 0.f;
#pragma unroll 8
        for (int k = 0; k < 2 * D; k++) {
            float4 wv = *(const float4*)&Wsm[k * D + l16 * 4];
            float a0 = A0[k], a1 = A1[k];
            acc00 += a0 * wv.x; acc01 += a0 * wv.y;
            acc02 += a0 * wv.z; acc03 += a0 * wv.w;
            acc10 += a1 * wv.x; acc11 += a1 * wv.y;
            acc12 += a1 * wv.z; acc13 += a1 * wv.w;
        }
        float4 bv = ((const float4*)bias)[l16];
        {
            int gr = row0 + half * 2;
            float4 o;
            o.x = acc00 + bv.x; o.y = acc01 + bv.y;
            o.z = acc02 + bv.z; o.w = acc03 + bv.w;
            if (RELU) { o.x = fmaxf(o.x, 0.f); o.y = fmaxf(o.y, 0.f);
                        o.z = fmaxf(o.z, 0.f); o.w = fmaxf(o.w, 0.f); }
            *(float4*)(outp + (long long)gr * D + l16 * 4) = o;
            gr++;
            o.x = acc10 + bv.x; o.y = acc11 + bv.y;
            o.z = acc12 + bv.z; o.w = acc13 + bv.w;
            if (RELU) { o.x = fmaxf(o.x, 0.f); o.y = fmaxf(o.y, 0.f);
                        o.z = fmaxf(o.z, 0.f); o.w = fmaxf(o.w, 0.f); }
            *(float4*)(outp + (long long)gr * D + l16 * 4) = o;
        }
        __syncwarp();   // protect Aw before next tile overwrites it
    }
}

// ---------------- fused persistent kernel ----------------
__global__ void __launch_bounds__(TPB, 4)
sage_fused_kernel(const float* __restrict__ x,
                  const void* __restrict__ srcp,
                  const void* __restrict__ dstp,
                  const float* __restrict__ W_self0, const float* __restrict__ W_neigh0,
                  const float* __restrict__ b0,
                  const float* __restrict__ W_self1, const float* __restrict__ W_neigh1,
                  const float* __restrict__ b1,
                  float* __restrict__ outp) {
    const int tid = threadIdx.x;
    const int bid = blockIdx.x;
    const int gtid = bid * TPB + tid;
    const int gstride = GRID * TPB;
    const int wid = tid >> 5;
    const int lane = tid & 31;

    __shared__ float Wsm[2 * D * D];              // 32 KB stacked [Wself; Wneigh]
    __shared__ float At[TPB / 32][TILE_ROWS][AT_STRIDE];  // 16.9 KB per-warp tiles
    __shared__ int   sscan[TPB];                  // scan scratch

    // ---- index dtype detection (every block computes identically) ----
    if (tid == 0) sscan[0] = 0;
    __syncthreads();
    {
        int any = 0;
        const int* si = (const int*)srcp;
        for (int i = tid; i < 2048; i += TPB) any |= si[2 * i + 1];
        if (any) atomicOr(&sscan[0], 1);
    }
    __syncthreads();
    const bool is64 = (sscan[0] == 0);   // high words all zero -> int64 little-endian

    // ---- phase A: zero counters ----
    for (int j = gtid; j < N_NODES; j += gstride) { g_degcnt[j] = 0; g_cursor[j] = 0; }
    if (gtid < 2) g_tile[gtid] = 0;
    grid_bar();

    // ---- phase B: degree histogram ----
    for (int e = gtid; e < N_EDGES; e += gstride)
        atomicAdd(&g_degcnt[load_idx(dstp, e, is64)], 1);
    grid_bar();

    // ---- phase C: per-block chunk sums ----
    {
        int n0 = bid * CH;
        int n = N_NODES - n0; if (n > CH) n = CH; if (n < 0) n = 0;
        int v = (tid < n) ? g_degcnt[n0 + tid] : 0;
        sscan[tid] = v; __syncthreads();
        for (int off = TPB / 2; off > 0; off >>= 1) {
            if (tid < off) sscan[tid] += sscan[tid + off];
            __syncthreads();
        }
        if (tid == 0) g_bsum[bid] = sscan[0];
    }
    grid_bar();

    // ---- phase D: block 0 scans the 592 chunk sums ----
    if (bid == 0) {
        int v[3]; int mysum = 0;
#pragma unroll
        for (int k = 0; k < 3; k++) {
            int idx = tid * 3 + k;
            v[k] = (idx < GRID) ? g_bsum[idx] : 0;
            mysum += v[k];
        }
        sscan[tid] = mysum; __syncthreads();
        for (int off = 1; off < TPB; off <<= 1) {
            int t = (tid >= off) ? sscan[tid - off] : 0;
            __syncthreads();
            sscan[tid] += t;
            __syncthreads();
        }
        int run = sscan[tid] - mysum;   // exclusive prefix of thread sums
#pragma unroll
        for (int k = 0; k < 3; k++) {
            int idx = tid * 3 + k;
            if (idx < GRID) g_boff[idx] = run;
            run += v[k];
        }
    }
    grid_bar();

    // ---- phase E: per-chunk exclusive scan -> row starts ----
    {
        int n0 = bid * CH;
        int n = N_NODES - n0; if (n > CH) n = CH; if (n < 0) n = 0;
        int v = (tid < n) ? g_degcnt[n0 + tid] : 0;
        sscan[tid] = v; __syncthreads();
        for (int off = 1; off < TPB; off <<= 1) {
            int t = (tid >= off) ? sscan[tid - off] : 0;
            __syncthreads();
            sscan[tid] += t;
            __syncthreads();
        }
        if (tid < n) g_rs[n0 + tid] = g_boff[bid] + sscan[tid] - v;
        if (bid == 0 && tid == 0) g_rs[N_NODES] = N_EDGES;
    }
    grid_bar();

    // ---- phase F: fill CSR ----
    for (int e = gtid; e < N_EDGES; e += gstride) {
        int dn = load_idx(dstp, e, is64);
        int s  = load_idx(srcp, e, is64);
        int pos = atomicAdd(&g_cursor[dn], 1);
        g_csr[g_rs[dn] + pos] = s;
    }
    grid_bar();

    // ---- phase G: layer 0 -> g_h (relu) ----
    {
#pragma unroll
        for (int j = 0; j < 4; j++) {
            int idx = tid + j * TPB;
            ((float4*)Wsm)[idx]        = ((const float4*)W_self0)[idx];
            ((float4*)Wsm)[idx + 1024] = ((const float4*)W_neigh0)[idx];
        }
        __syncthreads();
        run_layer<true>(x, g_h, b0, 0, At[wid], Wsm, lane);
    }
    grid_bar();

    // ---- phase H: layer 1 -> out (no relu) ----
    {
#pragma unroll
        for (int j = 0; j < 4; j++) {
            int idx = tid + j * TPB;
            ((float4*)Wsm)[idx]        = ((const float4*)W_self1)[idx];
            ((float4*)Wsm)[idx + 1024] = ((const float4*)W_neigh1)[idx];
        }
        __syncthreads();
        run_layer<false>(g_h, outp, b1, 1, At[wid], Wsm, lane);
    }
}

// ---------------- launch: ONE kernel = ONE graph node ----------------
extern "C" void kernel_launch(void* const* d_in, const int* in_sizes, int n_in,
                              void* d_out, int out_size) {
    const float* x        = (const float*)d_in[0];
    const void*  src      = d_in[1];
    const void*  dst      = d_in[2];
    const float* W_self0  = (const float*)d_in[3];
    const float* W_neigh0 = (const float*)d_in[4];
    const float* b0       = (const float*)d_in[5];
    const float* W_self1  = (const float*)d_in[6];
    const float* W_neigh1 = (const float*)d_in[7];
    const float* b1       = (const float*)d_in[8];
    float* outp = (float*)d_out;

    sage_fused_kernel<<<GRID, TPB>>>(x, src, dst,
                                     W_self0, W_neigh0, b0,
                                     W_self1, W_neigh1, b1, outp);
}